// round 10
// baseline (speedup 1.0000x reference)
#include <cuda_runtime.h>
#include <cuda_fp16.h>
#include <cstdint>

#define DEV __device__ __forceinline__

static constexpr int NROWS = 2048;
static constexpr int INF   = 4096;
static constexpr int OUTF  = 4096;

static constexpr int BM = 128, BN = 128, BK = 64;
static constexpr int STAGES = 3;                         // 3-deep ring
static constexpr int NIT = INF / BK;                     // 64
static constexpr int PITCH_H = 72;                       // halfs per smem row (64 + 8 pad)
static constexpr int PITCH_B = PITCH_H * 2;              // 144 bytes
static constexpr int A_BYTES = BM * PITCH_B;             // 18432
static constexpr int B_BYTES = BN * PITCH_B;             // 18432
static constexpr int STAGE_BYTES = A_BYTES + B_BYTES;    // 36864
static constexpr int SMEM_ALLOC = STAGES * STAGE_BYTES;  // 110592 (x2 CTAs = 216KB < 228KB)

// ---------------- scratch (no allocs allowed) ----------------
__device__ __align__(1024) __half g_wmean[(size_t)OUTF * INF];
__device__ __align__(1024) __half g_wvar [(size_t)OUTF * INF];
__device__ __align__(1024) __half g_xh   [(size_t)NROWS * INF];
__device__ __align__(1024) __half g_x2h  [(size_t)NROWS * INF];
__device__ float g_bmean[OUTF];
__device__ float g_bvar [OUTF];

// ---------------- PTX helpers ----------------
DEV uint32_t smem_u32(const void* p) {
    uint32_t a;
    asm("{ .reg .u64 t; cvta.to.shared.u64 t, %1; cvt.u32.u64 %0, t; }" : "=r"(a) : "l"(p));
    return a;
}
DEV void cp16(uint32_t saddr, const void* g) {
    asm volatile("cp.async.cg.shared.global [%0], [%1], 16;" :: "r"(saddr), "l"(g) : "memory");
}
DEV void ldm_x4(uint32_t* r, uint32_t addr) {
    asm volatile("ldmatrix.sync.aligned.m8n8.x4.shared.b16 {%0,%1,%2,%3}, [%4];"
                 : "=r"(r[0]), "=r"(r[1]), "=r"(r[2]), "=r"(r[3]) : "r"(addr));
}
DEV void mma16816(float* c, const uint32_t* a, uint32_t b0, uint32_t b1) {
    asm volatile(
        "mma.sync.aligned.m16n8k16.row.col.f32.f16.f16.f32 "
        "{%0,%1,%2,%3}, {%4,%5,%6,%7}, {%8,%9}, {%0,%1,%2,%3};"
        : "+f"(c[0]), "+f"(c[1]), "+f"(c[2]), "+f"(c[3])
        : "r"(a[0]), "r"(a[1]), "r"(a[2]), "r"(a[3]), "r"(b0), "r"(b1));
}

// ---------------- preprocessing ----------------
DEV void moments(float l0, float l1, float l2, float& mean, float& var) {
    float e0 = __expf(l0), e1 = __expf(l1), e2 = __expf(l2);
    float inv = 1.0f / (e0 + e1 + e2);
    float m  = (e2 - e0) * inv;
    float sq = (e2 + e0) * inv;
    mean = m;
    var  = sq - m * m;
}

__global__ void prep_w_kernel(const float* __restrict__ W) {
    const size_t P = (size_t)OUTF * INF;
    size_t i = ((size_t)blockIdx.x * blockDim.x + threadIdx.x) * 4;
    if (i >= P) return;
    float4 a = *(const float4*)(W + i);
    float4 b = *(const float4*)(W + P + i);
    float4 c = *(const float4*)(W + 2 * P + i);
    float m[4], v[4];
    moments(a.x, b.x, c.x, m[0], v[0]);
    moments(a.y, b.y, c.y, m[1], v[1]);
    moments(a.z, b.z, c.z, m[2], v[2]);
    moments(a.w, b.w, c.w, m[3], v[3]);
    __half2* pm = (__half2*)(g_wmean + i);
    pm[0] = __floats2half2_rn(m[0], m[1]);
    pm[1] = __floats2half2_rn(m[2], m[3]);
    __half2* pv = (__half2*)(g_wvar + i);
    pv[0] = __floats2half2_rn(v[0], v[1]);
    pv[1] = __floats2half2_rn(v[2], v[3]);
}

__global__ void prep_x_kernel(const float* __restrict__ x) {
    const size_t P = (size_t)NROWS * INF;
    size_t i = ((size_t)blockIdx.x * blockDim.x + threadIdx.x) * 4;
    if (i >= P) return;
    float4 a = *(const float4*)(x + i);
    __half2* ph = (__half2*)(g_xh + i);
    ph[0] = __floats2half2_rn(a.x, a.y);
    ph[1] = __floats2half2_rn(a.z, a.w);
    __half2* p2 = (__half2*)(g_x2h + i);
    p2[0] = __floats2half2_rn(a.x * a.x, a.y * a.y);
    p2[1] = __floats2half2_rn(a.z * a.z, a.w * a.w);
}

__global__ void prep_b_kernel(const float* __restrict__ B) {
    int o = blockIdx.x * blockDim.x + threadIdx.x;
    if (o >= OUTF) return;
    float m, v;
    moments(B[o], B[OUTF + o], B[2 * OUTF + o], m, v);
    g_bmean[o] = m;
    g_bvar[o]  = v;
}

// ---------------- GEMM ----------------
DEV void load_stage(char* smem, const char* gA, const char* gB, int cc, int tid) {
    char* sa  = smem + (cc % STAGES) * STAGE_BYTES;
    char* sbt = sa + A_BYTES;
    const char* ga = gA + (size_t)cc * (BK * 2);
    const char* gb = gB + (size_t)cc * (BK * 2);
    // 128 threads: one row per thread, 8 x 16B segments per row for A and B
    const int row = tid;
    const uint32_t sbase = (uint32_t)(row * PITCH_B);
    const size_t   gbase = (size_t)row * (INF * 2);
#pragma unroll
    for (int seg = 0; seg < 8; seg++) {
        cp16(smem_u32(sa  + sbase + seg * 16), ga + gbase + seg * 16);
        cp16(smem_u32(sbt + sbase + seg * 16), gb + gbase + seg * 16);
    }
}

__global__ void __launch_bounds__(128, 2)
gemm_kernel(float* __restrict__ out) {
    extern __shared__ char smem[];

    const int tid  = threadIdx.x;
    const int wid  = tid >> 5, lane = tid & 31;
    const int bn = blockIdx.x, bm = blockIdx.y, bz = blockIdx.z;

    const int wm = wid >> 1, wn = wid & 1;    // 2 x 2 warp grid
    const int m0 = wm * 64, n0 = wn * 64;     // warp tile 64 x 64

    const char* gA = (const char*)((bz == 0 ? g_xh    : g_x2h ) + (size_t)bm * BM * INF);
    const char* gB = (const char*)((bz == 0 ? g_wmean : g_wvar) + (size_t)bn * BN * INF);
    const float* bias = (bz == 0 ? g_bmean : g_bvar);

    float acc[4][8][4];
#pragma unroll
    for (int i = 0; i < 4; i++)
#pragma unroll
        for (int j = 0; j < 8; j++)
#pragma unroll
            for (int k = 0; k < 4; k++) acc[i][j][k] = 0.0f;

    // lane-dependent ldmatrix address offsets (bytes within a stage tile)
    const uint32_t a_off = (uint32_t)((m0 + (lane & 15)) * PITCH_B + (lane >> 4) * 16);
    const uint32_t b_off = (uint32_t)(A_BYTES + (n0 + (lane & 7) + ((lane >> 4) & 1) * 8) * PITCH_B
                                      + ((lane >> 3) & 1) * 16);
    const uint32_t smem_base = smem_u32(smem);

    // double-buffered register fragments (4 m-blocks, 4 n-ldm blocks)
    uint32_t afr[2][4][4];
    uint32_t bfr[2][4][4];

#define LOAD_A_FRAGS(buf, stage_u, koff)                                          \
    _Pragma("unroll")                                                             \
    for (int mb = 0; mb < 4; mb++)                                                \
        ldm_x4(afr[buf][mb], (stage_u) + a_off + (uint32_t)(mb * 16 * PITCH_B + (koff)));
#define LOAD_B_FRAGS(buf, stage_u, koff)                                          \
    _Pragma("unroll")                                                             \
    for (int nb = 0; nb < 4; nb++)                                                \
        ldm_x4(bfr[buf][nb], (stage_u) + b_off + (uint32_t)(nb * 16 * PITCH_B + (koff)));
#define MMA_BURST(buf)                                                            \
    _Pragma("unroll")                                                             \
    for (int mb = 0; mb < 4; mb++)                                                \
        _Pragma("unroll")                                                         \
        for (int nb = 0; nb < 4; nb++) {                                          \
            mma16816(acc[mb][2 * nb],     afr[buf][mb], bfr[buf][nb][0], bfr[buf][nb][1]); \
            mma16816(acc[mb][2 * nb + 1], afr[buf][mb], bfr[buf][nb][2], bfr[buf][nb][3]); \
        }

    // prologue: stages 0,1 in flight (one commit group each)
    load_stage(smem, gA, gB, 0, tid);
    asm volatile("cp.async.commit_group;" ::: "memory");
    load_stage(smem, gA, gB, 1, tid);
    asm volatile("cp.async.commit_group;" ::: "memory");
    asm volatile("cp.async.wait_group 1;" ::: "memory");   // stage 0 resident
    __syncthreads();

    // buf0 <- stage 0, k-step 0
    LOAD_A_FRAGS(0, smem_base, 0)
    LOAD_B_FRAGS(0, smem_base, 0)

#pragma unroll 1
    for (int it = 0; it < NIT; it++) {
        const uint32_t su = smem_base + (uint32_t)((it % STAGES) * STAGE_BYTES);
        const uint32_t nu = smem_base + (uint32_t)(((it + 1) % STAGES) * STAGE_BYTES);

        // k1 -> buf1 ; MMA k0 (buf0)
        LOAD_A_FRAGS(1, su, 32)
        LOAD_B_FRAGS(1, su, 32)
        MMA_BURST(0)

        // k2 -> buf0 ; MMA k1 (buf1)
        LOAD_A_FRAGS(0, su, 64)
        LOAD_B_FRAGS(0, su, 64)
        MMA_BURST(1)

        // k3 -> buf1 ; MMA k2 (buf0)
        LOAD_A_FRAGS(1, su, 96)
        LOAD_B_FRAGS(1, su, 96)
        MMA_BURST(0)

        // refill slot (it+2)%3 == (it-1)%3: stage it-1's last reads were in
        // iter it-1 before that iter's sync -> safe to write now.
        const int cc = it + 2;
        if (cc < NIT) load_stage(smem, gA, gB, cc, tid);
        asm volatile("cp.async.commit_group;" ::: "memory");
        // all but newest group done -> stage it+1 resident and visible
        asm volatile("cp.async.wait_group 1;" ::: "memory");
        __syncthreads();

        // next stage k0 -> buf0 (tail iteration reads stale smem, unused)
        LOAD_A_FRAGS(0, nu, 0)
        LOAD_B_FRAGS(0, nu, 0)
        // MMA k3 (buf1) — operands loaded pre-wait; drains across next
        // iteration's front-end work.
        MMA_BURST(1)
    }

    // epilogue: direct float2 stores with bias
    const int qr = lane >> 2, qc = lane & 3;
    const size_t row_stride = 2 * (size_t)OUTF;
#pragma unroll
    for (int mf = 0; mf < 4; mf++) {
        const int gm = bm * BM + m0 + mf * 16 + qr;
#pragma unroll
        for (int nf = 0; nf < 8; nf++) {
            const int gn = bn * BN + n0 + nf * 8 + qc * 2;
            const float2 bv = *(const float2*)(bias + gn);
            float* p0 = out + (size_t)gm * row_stride + (size_t)bz * OUTF + gn;
            float* p1 = p0 + 8 * row_stride;
            float2 v0 = { acc[mf][nf][0] + bv.x, acc[mf][nf][1] + bv.y };
            float2 v1 = { acc[mf][nf][2] + bv.x, acc[mf][nf][3] + bv.y };
            *(float2*)p0 = v0;
            *(float2*)p1 = v1;
        }
    }
#undef LOAD_A_FRAGS
#undef LOAD_B_FRAGS
#undef MMA_BURST
}

// ---------------- launch ----------------
extern "C" void kernel_launch(void* const* d_in, const int* in_sizes, int n_in,
                              void* d_out, int out_size) {
    const float *x = nullptr, *W = nullptr, *Bl = nullptr;
    for (int i = 0; i < n_in; i++) {
        long long s = in_sizes[i];
        if (s == (long long)NROWS * INF)          x  = (const float*)d_in[i];
        else if (s == 3LL * OUTF * INF)           W  = (const float*)d_in[i];
        else if (s == 3LL * OUTF)                 Bl = (const float*)d_in[i];
    }
    float* out = (float*)d_out;

    prep_w_kernel<<<(unsigned)(((size_t)OUTF * INF / 4 + 255) / 256), 256>>>(W);
    prep_x_kernel<<<(unsigned)(((size_t)NROWS * INF / 4 + 255) / 256), 256>>>(x);
    prep_b_kernel<<<(OUTF + 255) / 256, 256>>>(Bl);

    cudaFuncSetAttribute(gemm_kernel, cudaFuncAttributeMaxDynamicSharedMemorySize, SMEM_ALLOC);
    dim3 grid(OUTF / BN, NROWS / BM, 2);  // (32, 16, 2) = 1024 CTAs
    gemm_kernel<<<grid, 128, SMEM_ALLOC>>>(out);
}

// round 13
// speedup vs baseline: 1.3183x; 1.3183x over previous
#include <cuda_runtime.h>
#include <cuda_fp16.h>
#include <cstdint>

#define DEV __device__ __forceinline__

static constexpr int NROWS = 2048;
static constexpr int INF   = 4096;
static constexpr int OUTF  = 4096;

static constexpr int BM = 128, BN = 128, BK = 64;
static constexpr int STAGES = 3;                         // 3-deep ring
static constexpr int NIT = INF / BK;                     // 64
static constexpr int PITCH_H = 72;                       // halfs per smem row (64 + 8 pad)
static constexpr int PITCH_B = PITCH_H * 2;              // 144 bytes
static constexpr int A_BYTES = BM * PITCH_B;             // 18432
static constexpr int B_BYTES = BN * PITCH_B;             // 18432
static constexpr int STAGE_BYTES = A_BYTES + B_BYTES;    // 36864
static constexpr int SMEM_ALLOC = STAGES * STAGE_BYTES;  // 110592 (x2 CTAs = 216KB < 228KB)

// ---------------- scratch (no allocs allowed) ----------------
__device__ __align__(1024) __half g_wmean[(size_t)OUTF * INF];
__device__ __align__(1024) __half g_wvar [(size_t)OUTF * INF];
__device__ __align__(1024) __half g_xh   [(size_t)NROWS * INF];
__device__ __align__(1024) __half g_x2h  [(size_t)NROWS * INF];
__device__ float g_bmean[OUTF];
__device__ float g_bvar [OUTF];

// ---------------- PTX helpers ----------------
DEV uint32_t smem_u32(const void* p) {
    uint32_t a;
    asm("{ .reg .u64 t; cvta.to.shared.u64 t, %1; cvt.u32.u64 %0, t; }" : "=r"(a) : "l"(p));
    return a;
}
DEV void cp16(uint32_t saddr, const void* g) {
    asm volatile("cp.async.cg.shared.global [%0], [%1], 16;" :: "r"(saddr), "l"(g) : "memory");
}
DEV void ldm_x4(uint32_t* r, uint32_t addr) {
    asm volatile("ldmatrix.sync.aligned.m8n8.x4.shared.b16 {%0,%1,%2,%3}, [%4];"
                 : "=r"(r[0]), "=r"(r[1]), "=r"(r[2]), "=r"(r[3]) : "r"(addr));
}
DEV void mma16816(float* c, const uint32_t* a, uint32_t b0, uint32_t b1) {
    asm volatile(
        "mma.sync.aligned.m16n8k16.row.col.f32.f16.f16.f32 "
        "{%0,%1,%2,%3}, {%4,%5,%6,%7}, {%8,%9}, {%0,%1,%2,%3};"
        : "+f"(c[0]), "+f"(c[1]), "+f"(c[2]), "+f"(c[3])
        : "r"(a[0]), "r"(a[1]), "r"(a[2]), "r"(a[3]), "r"(b0), "r"(b1));
}

// ---------------- preprocessing (single fused kernel) ----------------
DEV void moments(float l0, float l1, float l2, float& mean, float& var) {
    float e0 = __expf(l0), e1 = __expf(l1), e2 = __expf(l2);
    float inv = 1.0f / (e0 + e1 + e2);
    float m  = (e2 - e0) * inv;
    float sq = (e2 + e0) * inv;
    mean = m;
    var  = sq - m * m;
}

static constexpr unsigned PREP_W_BLOCKS = (unsigned)((size_t)OUTF * INF / 4 / 256);  // 16384
static constexpr unsigned PREP_X_BLOCKS = (unsigned)((size_t)NROWS * INF / 4 / 256); // 2048
static constexpr unsigned PREP_B_BLOCKS = (OUTF + 255) / 256;                        // 16
static constexpr unsigned PREP_BLOCKS   = PREP_W_BLOCKS + PREP_X_BLOCKS + PREP_B_BLOCKS;

__global__ void __launch_bounds__(256)
prep_kernel(const float* __restrict__ W, const float* __restrict__ x,
            const float* __restrict__ B) {
    const unsigned b = blockIdx.x;
    if (b < PREP_W_BLOCKS) {
        const size_t P = (size_t)OUTF * INF;
        size_t i = ((size_t)b * 256 + threadIdx.x) * 4;
        float4 a = *(const float4*)(W + i);
        float4 c = *(const float4*)(W + P + i);
        float4 d = *(const float4*)(W + 2 * P + i);
        float m[4], v[4];
        moments(a.x, c.x, d.x, m[0], v[0]);
        moments(a.y, c.y, d.y, m[1], v[1]);
        moments(a.z, c.z, d.z, m[2], v[2]);
        moments(a.w, c.w, d.w, m[3], v[3]);
        __half2* pm = (__half2*)(g_wmean + i);
        pm[0] = __floats2half2_rn(m[0], m[1]);
        pm[1] = __floats2half2_rn(m[2], m[3]);
        __half2* pv = (__half2*)(g_wvar + i);
        pv[0] = __floats2half2_rn(v[0], v[1]);
        pv[1] = __floats2half2_rn(v[2], v[3]);
    } else if (b < PREP_W_BLOCKS + PREP_X_BLOCKS) {
        size_t i = ((size_t)(b - PREP_W_BLOCKS) * 256 + threadIdx.x) * 4;
        float4 a = *(const float4*)(x + i);
        __half2* ph = (__half2*)(g_xh + i);
        ph[0] = __floats2half2_rn(a.x, a.y);
        ph[1] = __floats2half2_rn(a.z, a.w);
        __half2* p2 = (__half2*)(g_x2h + i);
        p2[0] = __floats2half2_rn(a.x * a.x, a.y * a.y);
        p2[1] = __floats2half2_rn(a.z * a.z, a.w * a.w);
    } else {
        int o = (int)(b - PREP_W_BLOCKS - PREP_X_BLOCKS) * 256 + threadIdx.x;
        if (o < OUTF) {
            float m, v;
            moments(B[o], B[OUTF + o], B[2 * OUTF + o], m, v);
            g_bmean[o] = m;
            g_bvar[o]  = v;
        }
    }
}

// ---------------- GEMM ----------------
// half = 0 -> A tile rows, half = 1 -> B tile rows (8 x 16B segs per row/thread)
DEV void load_stage_half(char* smem, const char* gA, const char* gB, int cc,
                         int tid, int half) {
    char* sa = smem + (cc % STAGES) * STAGE_BYTES + half * A_BYTES;
    const char* g = (half == 0 ? gA : gB) + (size_t)cc * (BK * 2);
    const uint32_t sbase = (uint32_t)(tid * PITCH_B);
    const size_t   gbase = (size_t)tid * (INF * 2);
#pragma unroll
    for (int seg = 0; seg < 8; seg++)
        cp16(smem_u32(sa + sbase + seg * 16), g + gbase + seg * 16);
}

__global__ void __launch_bounds__(256, 2)
gemm_kernel(float* __restrict__ out) {
    extern __shared__ char smem[];

    const int tid  = threadIdx.x;
    const int wid  = tid >> 5, lane = tid & 31;
    const int bn = blockIdx.x, bm = blockIdx.y, bz = blockIdx.z;

    const int wm = wid >> 1, wn = wid & 1;    // 4 x 2 warp grid
    const int m0 = wm * 32, n0 = wn * 64;     // warp tile 32 x 64

    const char* gA = (const char*)((bz == 0 ? g_xh    : g_x2h ) + (size_t)bm * BM * INF);
    const char* gB = (const char*)((bz == 0 ? g_wmean : g_wvar) + (size_t)bn * BN * INF);
    const float* bias = (bz == 0 ? g_bmean : g_bvar);

    // each thread covers half the rows per load-half: rows 0..127 of A (tid<128
    // handled by tid%128 pattern) -- use tid for A rows when tid<128, B rows when tid>=128
    // (load_stage_half is called with 128-thread slices below)

    float acc[2][8][4];
#pragma unroll
    for (int i = 0; i < 2; i++)
#pragma unroll
        for (int j = 0; j < 8; j++)
#pragma unroll
            for (int k = 0; k < 4; k++) acc[i][j][k] = 0.0f;

    // lane-dependent ldmatrix address offsets (bytes within a stage tile)
    const uint32_t a_off = (uint32_t)((m0 + (lane & 15)) * PITCH_B + (lane >> 4) * 16);
    const uint32_t b_off = (uint32_t)(A_BYTES + (n0 + (lane & 7) + ((lane >> 4) & 1) * 8) * PITCH_B
                                      + ((lane >> 3) & 1) * 16);
    const uint32_t smem_base = smem_u32(smem);

    // 256 threads -> each load half uses all threads over 128 rows x 8 segs:
    // tid covers row tid>>1, segs (tid&1)*4 .. (tid&1)*4+3
    const int lrow = tid >> 1;
    const int lseg0 = (tid & 1) * 4;

#define LOAD_HALF(cc, half)                                                       \
    {                                                                             \
        char* sa_ = smem + ((cc) % STAGES) * STAGE_BYTES + (half) * A_BYTES;      \
        const char* g_ = ((half) == 0 ? gA : gB) + (size_t)(cc) * (BK * 2);       \
        const uint32_t sb_ = (uint32_t)(lrow * PITCH_B);                          \
        const size_t   gb_ = (size_t)lrow * (INF * 2);                            \
        _Pragma("unroll")                                                         \
        for (int s_ = 0; s_ < 4; s_++) {                                          \
            int seg_ = lseg0 + s_;                                                \
            cp16(smem_u32(sa_ + sb_ + seg_ * 16), g_ + gb_ + (size_t)seg_ * 16);  \
        }                                                                         \
    }

    // double-buffered register fragments
    uint32_t afr[2][2][4];
    uint32_t bfr[2][4][4];

#define LOAD_A_FRAGS(buf, stage_u, koff)                                          \
    _Pragma("unroll")                                                             \
    for (int mb = 0; mb < 2; mb++)                                                \
        ldm_x4(afr[buf][mb], (stage_u) + a_off + (uint32_t)(mb * 16 * PITCH_B + (koff)));
#define LOAD_B_FRAGS(buf, stage_u, koff)                                          \
    _Pragma("unroll")                                                             \
    for (int nb = 0; nb < 4; nb++)                                                \
        ldm_x4(bfr[buf][nb], (stage_u) + b_off + (uint32_t)(nb * 16 * PITCH_B + (koff)));
#define MMA_BURST(buf)                                                            \
    _Pragma("unroll")                                                             \
    for (int mb = 0; mb < 2; mb++)                                                \
        _Pragma("unroll")                                                         \
        for (int nb = 0; nb < 4; nb++) {                                          \
            mma16816(acc[mb][2 * nb],     afr[buf][mb], bfr[buf][nb][0], bfr[buf][nb][1]); \
            mma16816(acc[mb][2 * nb + 1], afr[buf][mb], bfr[buf][nb][2], bfr[buf][nb][3]); \
        }

    // prologue: stages 0,1 in flight (one commit group each)
    LOAD_HALF(0, 0) LOAD_HALF(0, 1)
    asm volatile("cp.async.commit_group;" ::: "memory");
    LOAD_HALF(1, 0) LOAD_HALF(1, 1)
    asm volatile("cp.async.commit_group;" ::: "memory");
    asm volatile("cp.async.wait_group 1;" ::: "memory");   // stage 0 resident
    __syncthreads();

    // buf0 <- stage 0, k-step 0
    LOAD_A_FRAGS(0, smem_base, 0)
    LOAD_B_FRAGS(0, smem_base, 0)

#pragma unroll 1
    for (int it = 0; it < NIT; it++) {
        const uint32_t su = smem_base + (uint32_t)((it % STAGES) * STAGE_BYTES);
        const uint32_t nu = smem_base + (uint32_t)(((it + 1) % STAGES) * STAGE_BYTES);
        const int cc = it + 2;
        const bool do_load = (cc < NIT);

        // k1 -> buf1 ; MMA k0 (buf0)
        LOAD_A_FRAGS(1, su, 32)
        LOAD_B_FRAGS(1, su, 32)
        // A-half of the refill, issued early: slot (it+2)%3==(it-1)%3 whose
        // last reads preceded iter it-1's sync -> safe from iter-it start.
        if (do_load) LOAD_HALF(cc, 0)
        MMA_BURST(0)

        // k2 -> buf0 ; MMA k1 (buf1)
        LOAD_A_FRAGS(0, su, 64)
        LOAD_B_FRAGS(0, su, 64)
        if (do_load) LOAD_HALF(cc, 1)      // B-half issued here
        MMA_BURST(1)

        // k3 -> buf1 ; MMA k2 (buf0)
        LOAD_A_FRAGS(1, su, 96)
        LOAD_B_FRAGS(1, su, 96)
        MMA_BURST(0)

        asm volatile("cp.async.commit_group;" ::: "memory");
        // all but newest group done -> stage it+1 resident and visible
        asm volatile("cp.async.wait_group 1;" ::: "memory");
        __syncthreads();

        // next stage k0 -> buf0 (tail iteration reads stale smem, unused)
        LOAD_A_FRAGS(0, nu, 0)
        LOAD_B_FRAGS(0, nu, 0)
        // MMA k3 (buf1) — operands loaded pre-wait; drains across next
        // iteration's front-end work.
        MMA_BURST(1)
    }

    // epilogue: direct float2 stores with bias
    const int qr = lane >> 2, qc = lane & 3;
    const size_t row_stride = 2 * (size_t)OUTF;
#pragma unroll
    for (int mf = 0; mf < 2; mf++) {
        const int gm = bm * BM + m0 + mf * 16 + qr;
#pragma unroll
        for (int nf = 0; nf < 8; nf++) {
            const int gn = bn * BN + n0 + nf * 8 + qc * 2;
            const float2 bv = *(const float2*)(bias + gn);
            float* p0 = out + (size_t)gm * row_stride + (size_t)bz * OUTF + gn;
            float* p1 = p0 + 8 * row_stride;
            float2 v0 = { acc[mf][nf][0] + bv.x, acc[mf][nf][1] + bv.y };
            float2 v1 = { acc[mf][nf][2] + bv.x, acc[mf][nf][3] + bv.y };
            *(float2*)p0 = v0;
            *(float2*)p1 = v1;
        }
    }
#undef LOAD_A_FRAGS
#undef LOAD_B_FRAGS
#undef MMA_BURST
#undef LOAD_HALF
}

// ---------------- launch ----------------
extern "C" void kernel_launch(void* const* d_in, const int* in_sizes, int n_in,
                              void* d_out, int out_size) {
    const float *x = nullptr, *W = nullptr, *Bl = nullptr;
    for (int i = 0; i < n_in; i++) {
        long long s = in_sizes[i];
        if (s == (long long)NROWS * INF)          x  = (const float*)d_in[i];
        else if (s == 3LL * OUTF * INF)           W  = (const float*)d_in[i];
        else if (s == 3LL * OUTF)                 Bl = (const float*)d_in[i];
    }
    float* out = (float*)d_out;

    prep_kernel<<<PREP_BLOCKS, 256>>>(W, x, Bl);

    cudaFuncSetAttribute(gemm_kernel, cudaFuncAttributeMaxDynamicSharedMemorySize, SMEM_ALLOC);
    dim3 grid(OUTF / BN, NROWS / BM, 2);  // (32, 16, 2) = 1024 CTAs
    gemm_kernel<<<grid, 256, SMEM_ALLOC>>>(out);
}

// round 14
// speedup vs baseline: 1.6703x; 1.2670x over previous
#include <cuda_runtime.h>
#include <cuda_fp16.h>
#include <cstdint>

#define DEV __device__ __forceinline__

static constexpr int NROWS = 2048;
static constexpr int INF   = 4096;
static constexpr int OUTF  = 4096;

static constexpr int BM = 128, BN = 128, BK = 64;
static constexpr int STAGES = 3;                         // 3-deep ring
static constexpr int NIT = INF / BK;                     // 64
static constexpr int PITCH_H = 72;                       // halfs per smem row (64 + 8 pad)
static constexpr int PITCH_B = PITCH_H * 2;              // 144 bytes
static constexpr int A_BYTES = BM * PITCH_B;             // 18432
static constexpr int B_BYTES = BN * PITCH_B;             // 18432
static constexpr int STAGE_BYTES = A_BYTES + B_BYTES;    // 36864
static constexpr int SMEM_ALLOC = STAGES * STAGE_BYTES;  // 110592 (x2 CTAs = 216KB < 228KB)

// ---------------- scratch (no allocs allowed) ----------------
__device__ __align__(1024) __half g_wmean[(size_t)OUTF * INF];
__device__ __align__(1024) __half g_wvar [(size_t)OUTF * INF];
__device__ __align__(1024) __half g_xh   [(size_t)NROWS * INF];
__device__ __align__(1024) __half g_x2h  [(size_t)NROWS * INF];
__device__ float g_bmean[OUTF];
__device__ float g_bvar [OUTF];

// ---------------- PTX helpers ----------------
DEV uint32_t smem_u32(const void* p) {
    uint32_t a;
    asm("{ .reg .u64 t; cvta.to.shared.u64 t, %1; cvt.u32.u64 %0, t; }" : "=r"(a) : "l"(p));
    return a;
}
DEV void cp16(uint32_t saddr, const void* g) {
    asm volatile("cp.async.cg.shared.global [%0], [%1], 16;" :: "r"(saddr), "l"(g) : "memory");
}
DEV void ldm_x4(uint32_t* r, uint32_t addr) {
    asm volatile("ldmatrix.sync.aligned.m8n8.x4.shared.b16 {%0,%1,%2,%3}, [%4];"
                 : "=r"(r[0]), "=r"(r[1]), "=r"(r[2]), "=r"(r[3]) : "r"(addr));
}
DEV void mma16816(float* c, const uint32_t* a, uint32_t b0, uint32_t b1) {
    asm volatile(
        "mma.sync.aligned.m16n8k16.row.col.f32.f16.f16.f32 "
        "{%0,%1,%2,%3}, {%4,%5,%6,%7}, {%8,%9}, {%0,%1,%2,%3};"
        : "+f"(c[0]), "+f"(c[1]), "+f"(c[2]), "+f"(c[3])
        : "r"(a[0]), "r"(a[1]), "r"(a[2]), "r"(a[3]), "r"(b0), "r"(b1));
}

// ---------------- preprocessing (single fused kernel) ----------------
DEV void moments(float l0, float l1, float l2, float& mean, float& var) {
    float e0 = __expf(l0), e1 = __expf(l1), e2 = __expf(l2);
    float inv = 1.0f / (e0 + e1 + e2);
    float m  = (e2 - e0) * inv;
    float sq = (e2 + e0) * inv;
    mean = m;
    var  = sq - m * m;
}

static constexpr unsigned PREP_W_BLOCKS = (unsigned)((size_t)OUTF * INF / 4 / 256);  // 16384
static constexpr unsigned PREP_X_BLOCKS = (unsigned)((size_t)NROWS * INF / 4 / 256); // 2048
static constexpr unsigned PREP_B_BLOCKS = (OUTF + 255) / 256;                        // 16
static constexpr unsigned PREP_BLOCKS   = PREP_W_BLOCKS + PREP_X_BLOCKS + PREP_B_BLOCKS;

__global__ void __launch_bounds__(256)
prep_kernel(const float* __restrict__ W, const float* __restrict__ x,
            const float* __restrict__ B) {
    const unsigned b = blockIdx.x;
    if (b < PREP_W_BLOCKS) {
        const size_t P = (size_t)OUTF * INF;
        size_t i = ((size_t)b * 256 + threadIdx.x) * 4;
        float4 a = *(const float4*)(W + i);
        float4 c = *(const float4*)(W + P + i);
        float4 d = *(const float4*)(W + 2 * P + i);
        float m[4], v[4];
        moments(a.x, c.x, d.x, m[0], v[0]);
        moments(a.y, c.y, d.y, m[1], v[1]);
        moments(a.z, c.z, d.z, m[2], v[2]);
        moments(a.w, c.w, d.w, m[3], v[3]);
        __half2* pm = (__half2*)(g_wmean + i);
        pm[0] = __floats2half2_rn(m[0], m[1]);
        pm[1] = __floats2half2_rn(m[2], m[3]);
        __half2* pv = (__half2*)(g_wvar + i);
        pv[0] = __floats2half2_rn(v[0], v[1]);
        pv[1] = __floats2half2_rn(v[2], v[3]);
    } else if (b < PREP_W_BLOCKS + PREP_X_BLOCKS) {
        size_t i = ((size_t)(b - PREP_W_BLOCKS) * 256 + threadIdx.x) * 4;
        float4 a = *(const float4*)(x + i);
        __half2* ph = (__half2*)(g_xh + i);
        ph[0] = __floats2half2_rn(a.x, a.y);
        ph[1] = __floats2half2_rn(a.z, a.w);
        __half2* p2 = (__half2*)(g_x2h + i);
        p2[0] = __floats2half2_rn(a.x * a.x, a.y * a.y);
        p2[1] = __floats2half2_rn(a.z * a.z, a.w * a.w);
    } else {
        int o = (int)(b - PREP_W_BLOCKS - PREP_X_BLOCKS) * 256 + threadIdx.x;
        if (o < OUTF) {
            float m, v;
            moments(B[o], B[OUTF + o], B[2 * OUTF + o], m, v);
            g_bmean[o] = m;
            g_bvar[o]  = v;
        }
    }
}

// ---------------- GEMM (R8 structure, byte-for-byte) ----------------
DEV void load_stage(char* smem, const char* gA, const char* gB, int cc, int tid) {
    char* sa  = smem + (cc % STAGES) * STAGE_BYTES;
    char* sbt = sa + A_BYTES;
    const char* ga = gA + (size_t)cc * (BK * 2);
    const char* gb = gB + (size_t)cc * (BK * 2);
#pragma unroll
    for (int i = 0; i < 4; i++) {
        int idx = tid + i * 256;              // 0..1023 over (row, 16B-seg)
        int row = idx >> 3, seg = idx & 7;
        uint32_t so = (uint32_t)(row * PITCH_B + seg * 16);
        size_t   go = (size_t)row * (INF * 2) + (size_t)seg * 16;
        cp16(smem_u32(sa  + so), ga + go);
        cp16(smem_u32(sbt + so), gb + go);
    }
}

__global__ void __launch_bounds__(256, 2)
gemm_kernel(float* __restrict__ out) {
    extern __shared__ char smem[];

    const int tid  = threadIdx.x;
    const int wid  = tid >> 5, lane = tid & 31;
    const int bn = blockIdx.x, bm = blockIdx.y, bz = blockIdx.z;

    const int wm = wid >> 1, wn = wid & 1;    // 4 x 2 warp grid
    const int m0 = wm * 32, n0 = wn * 64;     // warp tile 32 x 64

    const char* gA = (const char*)((bz == 0 ? g_xh    : g_x2h ) + (size_t)bm * BM * INF);
    const char* gB = (const char*)((bz == 0 ? g_wmean : g_wvar) + (size_t)bn * BN * INF);
    const float* bias = (bz == 0 ? g_bmean : g_bvar);

    float acc[2][8][4];
#pragma unroll
    for (int i = 0; i < 2; i++)
#pragma unroll
        for (int j = 0; j < 8; j++)
#pragma unroll
            for (int k = 0; k < 4; k++) acc[i][j][k] = 0.0f;

    // lane-dependent ldmatrix address offsets (bytes within a stage tile)
    const uint32_t a_off = (uint32_t)((m0 + (lane & 15)) * PITCH_B + (lane >> 4) * 16);
    const uint32_t b_off = (uint32_t)(A_BYTES + (n0 + (lane & 7) + ((lane >> 4) & 1) * 8) * PITCH_B
                                      + ((lane >> 3) & 1) * 16);
    const uint32_t smem_base = smem_u32(smem);

    // double-buffered register fragments
    uint32_t afr[2][2][4];
    uint32_t bfr[2][4][4];

#define LOAD_A_FRAGS(buf, stage_u, koff)                                          \
    _Pragma("unroll")                                                             \
    for (int mb = 0; mb < 2; mb++)                                                \
        ldm_x4(afr[buf][mb], (stage_u) + a_off + (uint32_t)(mb * 16 * PITCH_B + (koff)));
#define LOAD_B_FRAGS(buf, stage_u, koff)                                          \
    _Pragma("unroll")                                                             \
    for (int nb = 0; nb < 4; nb++)                                                \
        ldm_x4(bfr[buf][nb], (stage_u) + b_off + (uint32_t)(nb * 16 * PITCH_B + (koff)));
#define MMA_BURST(buf)                                                            \
    _Pragma("unroll")                                                             \
    for (int mb = 0; mb < 2; mb++)                                                \
        _Pragma("unroll")                                                         \
        for (int nb = 0; nb < 4; nb++) {                                          \
            mma16816(acc[mb][2 * nb],     afr[buf][mb], bfr[buf][nb][0], bfr[buf][nb][1]); \
            mma16816(acc[mb][2 * nb + 1], afr[buf][mb], bfr[buf][nb][2], bfr[buf][nb][3]); \
        }

    // prologue: stages 0,1 in flight (one commit group each)
    load_stage(smem, gA, gB, 0, tid);
    asm volatile("cp.async.commit_group;" ::: "memory");
    load_stage(smem, gA, gB, 1, tid);
    asm volatile("cp.async.commit_group;" ::: "memory");
    asm volatile("cp.async.wait_group 1;" ::: "memory");   // stage 0 resident
    __syncthreads();

    // buf0 <- stage 0, k-step 0
    LOAD_A_FRAGS(0, smem_base, 0)
    LOAD_B_FRAGS(0, smem_base, 0)

#pragma unroll 1
    for (int it = 0; it < NIT; it++) {
        const uint32_t su = smem_base + (uint32_t)((it % STAGES) * STAGE_BYTES);
        const uint32_t nu = smem_base + (uint32_t)(((it + 1) % STAGES) * STAGE_BYTES);

        // k1 -> buf1 ; MMA k0 (buf0)
        LOAD_A_FRAGS(1, su, 32)
        LOAD_B_FRAGS(1, su, 32)
        MMA_BURST(0)

        // k2 -> buf0 ; MMA k1 (buf1)
        LOAD_A_FRAGS(0, su, 64)
        LOAD_B_FRAGS(0, su, 64)
        MMA_BURST(1)

        // k3 -> buf1 ; MMA k2 (buf0)
        LOAD_A_FRAGS(1, su, 96)
        LOAD_B_FRAGS(1, su, 96)
        MMA_BURST(0)

        // refill slot (it+2)%3 == (it-1)%3: stage it-1's last reads were in
        // iter it-1 before that iter's sync -> safe to write now (R2 pattern).
        const int cc = it + 2;
        if (cc < NIT) load_stage(smem, gA, gB, cc, tid);
        asm volatile("cp.async.commit_group;" ::: "memory");
        // all but newest group done -> stage it+1 resident and visible
        asm volatile("cp.async.wait_group 1;" ::: "memory");
        __syncthreads();

        // next stage k0 -> buf0 (tail iteration reads stale smem, unused)
        LOAD_A_FRAGS(0, nu, 0)
        LOAD_B_FRAGS(0, nu, 0)
        // MMA k3 (buf1) — operands loaded pre-wait; drains across next
        // iteration's front-end work.
        MMA_BURST(1)
    }

    // epilogue: direct float2 stores with bias
    const int qr = lane >> 2, qc = lane & 3;
    const size_t row_stride = 2 * (size_t)OUTF;
#pragma unroll
    for (int mf = 0; mf < 2; mf++) {
        const int gm = bm * BM + m0 + mf * 16 + qr;
#pragma unroll
        for (int nf = 0; nf < 8; nf++) {
            const int gn = bn * BN + n0 + nf * 8 + qc * 2;
            const float2 bv = *(const float2*)(bias + gn);
            float* p0 = out + (size_t)gm * row_stride + (size_t)bz * OUTF + gn;
            float* p1 = p0 + 8 * row_stride;
            float2 v0 = { acc[mf][nf][0] + bv.x, acc[mf][nf][1] + bv.y };
            float2 v1 = { acc[mf][nf][2] + bv.x, acc[mf][nf][3] + bv.y };
            *(float2*)p0 = v0;
            *(float2*)p1 = v1;
        }
    }
#undef LOAD_A_FRAGS
#undef LOAD_B_FRAGS
#undef MMA_BURST
}

// ---------------- launch ----------------
extern "C" void kernel_launch(void* const* d_in, const int* in_sizes, int n_in,
                              void* d_out, int out_size) {
    const float *x = nullptr, *W = nullptr, *Bl = nullptr;
    for (int i = 0; i < n_in; i++) {
        long long s = in_sizes[i];
        if (s == (long long)NROWS * INF)          x  = (const float*)d_in[i];
        else if (s == 3LL * OUTF * INF)           W  = (const float*)d_in[i];
        else if (s == 3LL * OUTF)                 Bl = (const float*)d_in[i];
    }
    float* out = (float*)d_out;

    prep_kernel<<<PREP_BLOCKS, 256>>>(W, x, Bl);

    cudaFuncSetAttribute(gemm_kernel, cudaFuncAttributeMaxDynamicSharedMemorySize, SMEM_ALLOC);
    dim3 grid(OUTF / BN, NROWS / BM, 2);  // (32, 16, 2) = 1024 CTAs
    gemm_kernel<<<grid, 256, SMEM_ALLOC>>>(out);
}